// round 3
// baseline (speedup 1.0000x reference)
#include <cuda_runtime.h>
#include <cuda_bf16.h>
#include <cstdint>

// Problem constants
#define EMBD   2048
#define HEADS  8
#define HDIM   256          // EMB / HEADS
#define BATCH  2
#define SEQ    2048
#define BN_ROWS (BATCH*SEQ)     // 4096
#define QKV_N  (3*EMBD)         // 6144
#define NBH    (BATCH*HEADS)    // 16

// Scratch (device globals — no runtime allocation allowed)
__device__ float g_q [(size_t)NBH * SEQ * HDIM];   //  33.5 MB  [bh][n][d]
__device__ float g_kT[(size_t)NBH * HDIM * SEQ];   //  33.5 MB  [bh][d][n]
__device__ float g_v [(size_t)NBH * SEQ * HDIM];   //  33.5 MB  [bh][n][d]
__device__ float g_s [(size_t)NBH * SEQ * SEQ];    // 268  MB  [bh][q][k]
__device__ float g_o [(size_t)BN_ROWS * EMBD];     //  33.5 MB  [b*n][h*d]

// ---------------------------------------------------------------------------
// Tiled SGEMM: 128x128 block tile, BK=8, 256 threads, 8x8 per thread.
// MODE 0: qkv   = x @ w_qkv + b_qkv, scatter to g_q / g_kT / g_v
// MODE 1: g_s   = Q @ K^T      (batched over z = bh, K^T prestaged as g_kT)
// MODE 2: g_o   = P @ V        (batched over z = bh, writes [b,n,h*d] layout)
// MODE 3: out   = g_o @ w_proj + b_proj
// All shapes divide the tile exactly — no bounds checks.
// ---------------------------------------------------------------------------
template <int MODE>
__global__ __launch_bounds__(256, 2)
void gemm_k(const float* __restrict__ Ain, const float* __restrict__ Bin,
            const float* __restrict__ bias, float* __restrict__ Cout)
{
    constexpr int K   = (MODE == 1) ? HDIM : ((MODE == 2) ? SEQ : EMBD);
    constexpr int N   = (MODE == 0) ? QKV_N : ((MODE == 1) ? SEQ :
                        (MODE == 2) ? HDIM : EMBD);
    constexpr int LDC = (MODE == 2) ? EMBD : N;

    const int z = blockIdx.z;

    const float* A;
    const float* B;
    float*       C = nullptr;
    if (MODE == 0) {
        A = Ain;  B = Bin;                           // scatter epilogue, C unused
    } else if (MODE == 1) {
        A = g_q  + (size_t)z * SEQ * HDIM;
        B = g_kT + (size_t)z * HDIM * SEQ;
        C = g_s  + (size_t)z * SEQ * SEQ;
    } else if (MODE == 2) {
        A = g_s  + (size_t)z * SEQ * SEQ;
        B = g_v  + (size_t)z * SEQ * HDIM;
        C = g_o  + (size_t)(z >> 3) * SEQ * EMBD + (size_t)(z & 7) * HDIM;
    } else {
        A = g_o;  B = Bin;  C = Cout;
    }

    __shared__ float As[8][128];
    __shared__ float Bs[8][128];

    const int tid      = threadIdx.x;
    const int rowBase  = (tid >> 4) << 3;      // 0..120
    const int colBase  = (tid & 15) << 3;      // 0..120
    const int blockRow = blockIdx.y * 128;
    const int blockCol = blockIdx.x * 128;

    // A staging: each thread loads one float4 of A (row = tid/2, col = (tid&1)*4)
    const int arow = tid >> 1;
    const int acol = (tid & 1) << 2;
    // B staging: each thread loads one float4 of B (row = tid/32, col = (tid&31)*4)
    const int brow = tid >> 5;
    const int bcol = (tid & 31) << 2;

    const float* Aptr = A + (size_t)(blockRow + arow) * K + acol;
    const float* Bptr = B + (size_t)brow * N + blockCol + bcol;

    float acc[8][8];
    #pragma unroll
    for (int i = 0; i < 8; i++)
        #pragma unroll
        for (int j = 0; j < 8; j++) acc[i][j] = 0.0f;

    // register prefetch of first tile
    float4 av = *(const float4*)Aptr;
    float4 bv = *(const float4*)Bptr;

    for (int k0 = 0; k0 < K; k0 += 8) {
        As[acol + 0][arow] = av.x;
        As[acol + 1][arow] = av.y;
        As[acol + 2][arow] = av.z;
        As[acol + 3][arow] = av.w;
        *(float4*)&Bs[brow][bcol] = bv;
        __syncthreads();

        if (k0 + 8 < K) {           // issue next tile's LDGs before compute
            Aptr += 8;
            Bptr += (size_t)8 * N;
            av = *(const float4*)Aptr;
            bv = *(const float4*)Bptr;
        }

        #pragma unroll
        for (int kk = 0; kk < 8; kk++) {
            float4 a0 = *(const float4*)&As[kk][rowBase];
            float4 a1 = *(const float4*)&As[kk][rowBase + 4];
            float4 b0 = *(const float4*)&Bs[kk][colBase];
            float4 b1 = *(const float4*)&Bs[kk][colBase + 4];
            float a[8] = {a0.x, a0.y, a0.z, a0.w, a1.x, a1.y, a1.z, a1.w};
            float b[8] = {b0.x, b0.y, b0.z, b0.w, b1.x, b1.y, b1.z, b1.w};
            #pragma unroll
            for (int i = 0; i < 8; i++)
                #pragma unroll
                for (int j = 0; j < 8; j++)
                    acc[i][j] = fmaf(a[i], b[j], acc[i][j]);
        }
        __syncthreads();
    }

    // ---------------- epilogue ----------------
    if (MODE == 0) {
        // qkv column j = (h*HDIM + d)*3 + which
        #pragma unroll
        for (int i = 0; i < 8; i++) {
            const int gi = blockRow + rowBase + i;
            const int bb = gi >> 11;            // / SEQ
            const int ni = gi & (SEQ - 1);
            #pragma unroll
            for (int j = 0; j < 8; j++) {
                const int gj    = blockCol + colBase + j;
                const float val = acc[i][j] + bias[gj];
                const int which = gj % 3;
                const int tt    = gj / 3;
                const int h     = tt >> 8;       // / HDIM
                const int d     = tt & (HDIM - 1);
                const int bh    = (bb << 3) + h;
                if (which == 0)
                    g_q[((size_t)bh * SEQ + ni) * HDIM + d] = val;
                else if (which == 1)
                    g_kT[((size_t)bh * HDIM + d) * SEQ + ni] = val;
                else
                    g_v[((size_t)bh * SEQ + ni) * HDIM + d] = val;
            }
        }
    } else {
        #pragma unroll
        for (int i = 0; i < 8; i++) {
            const int gi = blockRow + rowBase + i;
            float* crow = C + (size_t)gi * LDC + blockCol + colBase;
            #pragma unroll
            for (int j4 = 0; j4 < 8; j4 += 4) {
                float4 v;
                if (MODE == 3) {
                    const int gj = blockCol + colBase + j4;
                    v.x = acc[i][j4 + 0] + bias[gj + 0];
                    v.y = acc[i][j4 + 1] + bias[gj + 1];
                    v.z = acc[i][j4 + 2] + bias[gj + 2];
                    v.w = acc[i][j4 + 3] + bias[gj + 3];
                } else {
                    v.x = acc[i][j4 + 0];
                    v.y = acc[i][j4 + 1];
                    v.z = acc[i][j4 + 2];
                    v.w = acc[i][j4 + 3];
                }
                *(float4*)&crow[j4] = v;
            }
        }
    }
}

// ---------------------------------------------------------------------------
// Row softmax over g_s, fused with the post-softmax 1/sqrt(EMB) scaling.
// One block per row (256 threads, 8 values/thread, single read + single write).
// ---------------------------------------------------------------------------
__global__ __launch_bounds__(256)
void softmax_k()
{
    constexpr int   N         = SEQ;
    constexpr float INV_SCALE = 0.02209708691207961f;   // 1/sqrt(2048)

    float* p = g_s + (size_t)blockIdx.x * N;
    const int t = threadIdx.x;
    const int w = t >> 5;
    const int l = t & 31;

    float v[8];
    float m = -3.0e38f;
    #pragma unroll
    for (int u = 0; u < 8; u++) {
        v[u] = p[t + 256 * u];
        m = fmaxf(m, v[u]);
    }
    #pragma unroll
    for (int o = 16; o > 0; o >>= 1)
        m = fmaxf(m, __shfl_xor_sync(0xffffffffu, m, o));

    __shared__ float redm[8];
    __shared__ float reds[8];
    if (l == 0) redm[w] = m;
    __syncthreads();
    m = redm[0];
    #pragma unroll
    for (int i = 1; i < 8; i++) m = fmaxf(m, redm[i]);

    float s = 0.0f;
    #pragma unroll
    for (int u = 0; u < 8; u++) {
        v[u] = __expf(v[u] - m);
        s += v[u];
    }
    #pragma unroll
    for (int o = 16; o > 0; o >>= 1)
        s += __shfl_xor_sync(0xffffffffu, s, o);
    if (l == 0) reds[w] = s;
    __syncthreads();
    s = reds[0];
    #pragma unroll
    for (int i = 1; i < 8; i++) s += reds[i];

    const float r = INV_SCALE / s;
    #pragma unroll
    for (int u = 0; u < 8; u++)
        p[t + 256 * u] = v[u] * r;
}

// ---------------------------------------------------------------------------
extern "C" void kernel_launch(void* const* d_in, const int* in_sizes, int n_in,
                              void* d_out, int out_size)
{
    const float* x      = (const float*)d_in[0];
    const float* w_qkv  = (const float*)d_in[1];
    const float* b_qkv  = (const float*)d_in[2];
    const float* w_proj = (const float*)d_in[3];
    const float* b_proj = (const float*)d_in[4];
    float*       out    = (float*)d_out;

    // 1) QKV projection + de-interleave into Q / K^T / V
    gemm_k<0><<<dim3(QKV_N / 128, BN_ROWS / 128, 1), 256>>>(x, w_qkv, b_qkv, nullptr);
    // 2) scores S = Q @ K^T  (per bh)
    gemm_k<1><<<dim3(SEQ / 128, SEQ / 128, NBH), 256>>>(nullptr, nullptr, nullptr, nullptr);
    // 3) softmax rows (folds 1/sqrt(EMB))
    softmax_k<<<NBH * SEQ, 256>>>();
    // 4) O = P @ V, written in [b, n, h*d] layout
    gemm_k<2><<<dim3(HDIM / 128, SEQ / 128, NBH), 256>>>(nullptr, nullptr, nullptr, nullptr);
    // 5) final projection + bias
    gemm_k<3><<<dim3(EMBD / 128, BN_ROWS / 128, 1), 256>>>(nullptr, w_proj, b_proj, out);
}